// round 2
// baseline (speedup 1.0000x reference)
#include <cuda_runtime.h>
#include <cstdint>

#define SQ 2048   // sequence length
#define NB 64     // batch
#define NH 256    // hidden
#define NI 256    // input
#define NO 256    // output

typedef unsigned long long ull;

// ---------------- packed f32x2 helpers ----------------
__device__ __forceinline__ ull f2fma(ull a, ull b, ull c) {
    ull d;
    asm("fma.rn.f32x2 %0, %1, %2, %3;" : "=l"(d) : "l"(a), "l"(b), "l"(c));
    return d;
}
__device__ __forceinline__ ull f2dup(float a) {
    ull d; unsigned ai = __float_as_uint(a);
    asm("mov.b64 %0, {%1, %2};" : "=l"(d) : "r"(ai), "r"(ai));
    return d;
}
__device__ __forceinline__ float f2sum(ull a) {
    unsigned lo, hi;
    asm("mov.b64 {%0, %1}, %2;" : "=r"(lo), "=r"(hi) : "l"(a));
    return __uint_as_float(lo) + __uint_as_float(hi);
}
__device__ __forceinline__ float2 f2unpack(ull a) {
    unsigned lo, hi;
    asm("mov.b64 {%0, %1}, %2;" : "=r"(lo), "=r"(hi) : "l"(a));
    return make_float2(__uint_as_float(lo), __uint_as_float(hi));
}

// ---------------- device scratch (allocations forbidden) ----------------
// Gx layout: [g][m][j], m = b*SQ + t   (g = 0:r, 1:z, 2:h)
__device__ float g_Gx[3ull * NB * SQ * NH];
// hs layout: [t][b][j]
__device__ float g_hs[(size_t)SQ * NB * NH];

// =====================================================================
// Phase 1: Gx[g][b*SQ+t][j] = sum_i x[b,t,i]*W_g[j,i] + b_g[j]
// 64x64 tile, K-tile 16, 256 threads, 4x4 micro-tile with f32x2.
// =====================================================================
__global__ void __launch_bounds__(256) gemm_pre(
    const float* __restrict__ x,
    const float* __restrict__ Wr, const float* __restrict__ Wz, const float* __restrict__ Wh,
    const float* __restrict__ br, const float* __restrict__ bz, const float* __restrict__ bh)
{
    const int g = blockIdx.z;
    const float* W    = (g == 0) ? Wr : ((g == 1) ? Wz : Wh);
    const float* bias = (g == 0) ? br : ((g == 1) ? bz : bh);

    const int m0 = blockIdx.x * 64;
    const int j0 = blockIdx.y * 64;
    const int tid = threadIdx.x;
    const int tx = tid & 15;
    const int ty = tid >> 4;

    __shared__ __align__(16) float sA[64 * 20];   // [m][k], row pad 20
    __shared__ __align__(16) float sB[16 * 68];   // [k][j], row pad 68

    ull acc[4][2];
    #pragma unroll
    for (int r = 0; r < 4; r++) { acc[r][0] = 0ull; acc[r][1] = 0ull; }

    const int rm = tid >> 2;   // 0..63
    const int kc = tid & 3;    // 0..3

    for (int kt = 0; kt < 16; kt++) {
        float4 a4 = *(const float4*)&x[(size_t)(m0 + rm) * NI + kt * 16 + kc * 4];
        *(float4*)&sA[rm * 20 + kc * 4] = a4;
        float4 b4 = *(const float4*)&W[(size_t)(j0 + rm) * (NI + NH) + kt * 16 + kc * 4];
        sB[(kc * 4 + 0) * 68 + rm] = b4.x;
        sB[(kc * 4 + 1) * 68 + rm] = b4.y;
        sB[(kc * 4 + 2) * 68 + rm] = b4.z;
        sB[(kc * 4 + 3) * 68 + rm] = b4.w;
        __syncthreads();

        #pragma unroll
        for (int kk = 0; kk < 16; kk++) {
            ulonglong2 b2 = *(const ulonglong2*)&sB[kk * 68 + tx * 4];
            #pragma unroll
            for (int r = 0; r < 4; r++) {
                ull ad = f2dup(sA[(ty * 4 + r) * 20 + kk]);
                acc[r][0] = f2fma(ad, b2.x, acc[r][0]);
                acc[r][1] = f2fma(ad, b2.y, acc[r][1]);
            }
        }
        __syncthreads();
    }

    const int jc = j0 + tx * 4;
    float4 bias4 = *(const float4*)&bias[jc];
    #pragma unroll
    for (int r = 0; r < 4; r++) {
        int m = m0 + ty * 4 + r;
        float2 p0 = f2unpack(acc[r][0]);
        float2 p1 = f2unpack(acc[r][1]);
        float4 v;
        v.x = p0.x + bias4.x; v.y = p0.y + bias4.y;
        v.z = p1.x + bias4.z; v.w = p1.y + bias4.w;
        *(float4*)&g_Gx[((size_t)g * (NB * SQ) + m) * NH + jc] = v;
    }
}

// =====================================================================
// Phase 3: out[b][s][o] = sum_h hs[s,b,h]*W_fc[o,h] + b_fc[o]
// =====================================================================
__global__ void __launch_bounds__(256) gemm_fc(
    const float* __restrict__ Wfc, const float* __restrict__ bfc,
    float* __restrict__ out)
{
    const int m0 = blockIdx.x * 64;
    const int j0 = blockIdx.y * 64;
    const int tid = threadIdx.x;
    const int tx = tid & 15;
    const int ty = tid >> 4;

    __shared__ __align__(16) float sA[64 * 20];
    __shared__ __align__(16) float sB[16 * 68];

    ull acc[4][2];
    #pragma unroll
    for (int r = 0; r < 4; r++) { acc[r][0] = 0ull; acc[r][1] = 0ull; }

    const int rm = tid >> 2;
    const int kc = tid & 3;

    for (int kt = 0; kt < 16; kt++) {
        float4 a4 = *(const float4*)&g_hs[(size_t)(m0 + rm) * NH + kt * 16 + kc * 4];
        *(float4*)&sA[rm * 20 + kc * 4] = a4;
        float4 b4 = *(const float4*)&Wfc[(size_t)(j0 + rm) * NH + kt * 16 + kc * 4];
        sB[(kc * 4 + 0) * 68 + rm] = b4.x;
        sB[(kc * 4 + 1) * 68 + rm] = b4.y;
        sB[(kc * 4 + 2) * 68 + rm] = b4.z;
        sB[(kc * 4 + 3) * 68 + rm] = b4.w;
        __syncthreads();

        #pragma unroll
        for (int kk = 0; kk < 16; kk++) {
            ulonglong2 b2 = *(const ulonglong2*)&sB[kk * 68 + tx * 4];
            #pragma unroll
            for (int r = 0; r < 4; r++) {
                ull ad = f2dup(sA[(ty * 4 + r) * 20 + kk]);
                acc[r][0] = f2fma(ad, b2.x, acc[r][0]);
                acc[r][1] = f2fma(ad, b2.y, acc[r][1]);
            }
        }
        __syncthreads();
    }

    const int jc = j0 + tx * 4;
    float4 bias4 = *(const float4*)&bfc[jc];
    #pragma unroll
    for (int r = 0; r < 4; r++) {
        int m = m0 + ty * 4 + r;          // m = s*NB + b
        int b = m & (NB - 1);
        int s = m >> 6;
        float2 p0 = f2unpack(acc[r][0]);
        float2 p1 = f2unpack(acc[r][1]);
        float4 v;
        v.x = p0.x + bias4.x; v.y = p0.y + bias4.y;
        v.z = p1.x + bias4.z; v.w = p1.y + bias4.w;
        *(float4*)&out[((size_t)b * SQ + s) * NO + jc] = v;
    }
}

// =====================================================================
// Phase 2: persistent recurrent kernel. 16 clusters x 8 CTAs.
// Cluster c: batches [4c, 4c+4). CTA rank r: output cols [32r, 32r+32),
// recurrent weight slices (fp32) resident in smem. h and r*h exchanged
// via DSMEM st.shared::cluster; 2 cluster barriers per step.
// Matvec thread map: s = tid&15 (k-slice), cp = tid>>4 (col pair).
// Each thread: 2 cols x 4 batches, k in {32i+2s, 32i+2s+1 : i=0..7}.
// =====================================================================
#define P2_SMEM_BYTES (30720 * 4)

__global__ void __cluster_dims__(8, 1, 1) __launch_bounds__(256, 1)
gru_rec(const float* __restrict__ Wr, const float* __restrict__ Wz,
        const float* __restrict__ Wh, float* __restrict__ hlast)
{
    extern __shared__ float sm[];
    float* sW    = sm;            // [3][32][256]  = 24576 floats
    float* sH    = sm + 24576;    // [4][256]
    float* sRH   = sm + 25600;    // [4][256]
    float* sPart = sm + 26624;    // [2][4][32][16] = 4096 floats

    const int tid  = threadIdx.x;
    const int rank = blockIdx.x & 7;
    const int b0   = (blockIdx.x >> 3) * 4;
    const int j0   = rank * 32;

    const int s   = tid & 15;     // k-slice
    const int cp  = tid >> 4;     // col pair 0..15
    const int jl0 = 2 * cp, jl1 = 2 * cp + 1;

    const int rb = tid >> 5;      // reduction: batch (tid<128)
    const int rc = tid & 31;      // reduction: local col

    // load recurrent weight slices (h-part: cols 256..511 of W_*)
    for (int idx = tid; idx < 32 * 256; idx += 256) {
        int jj = idx >> 8, k = idx & 255;
        size_t row = (size_t)(j0 + jj) * (NI + NH) + NI + k;
        sW[(0 * 32 + jj) * 256 + k] = Wr[row];
        sW[(1 * 32 + jj) * 256 + k] = Wz[row];
        sW[(2 * 32 + jj) * 256 + k] = Wh[row];
    }
    for (int idx = tid; idx < 1024; idx += 256) sH[idx] = 0.0f;
    __syncthreads();

    // DSMEM peer addresses (used by reduction threads tid<128)
    uint32_t rh_peer[8], h_peer[8];
    {
        uint32_t rha = (uint32_t)__cvta_generic_to_shared(&sRH[rb * 256 + j0 + rc]);
        uint32_t ha  = (uint32_t)__cvta_generic_to_shared(&sH [rb * 256 + j0 + rc]);
        #pragma unroll
        for (int p = 0; p < 8; p++) {
            asm("mapa.shared::cluster.u32 %0, %1, %2;" : "=r"(rh_peer[p]) : "r"(rha), "r"(p));
            asm("mapa.shared::cluster.u32 %0, %1, %2;" : "=r"(h_peer[p])  : "r"(ha),  "r"(p));
        }
    }

    asm volatile("barrier.cluster.arrive.aligned;" ::: "memory");
    asm volatile("barrier.cluster.wait.aligned;"   ::: "memory");

    float zloc = 0.0f, hloc = 0.0f;

    #pragma unroll 1
    for (int t = 0; t < SQ; t++) {
        // prefetch x-part preactivations (consumed at reductions, ~1000 cyc later)
        float gxr = 0.f, gxz = 0.f, gxh = 0.f;
        if (tid < 128) {
            size_t base = ((size_t)(b0 + rb) * SQ + t) * NH + j0 + rc;
            gxr = g_Gx[base];
            gxz = g_Gx[(size_t)(NB * SQ) * NH + base];
            gxh = g_Gx[2ull * (NB * SQ) * NH + base];
        }

        // ---- phase A: r,z matvec over sH ----
        ull aR0[4], aR1[4], aZ0[4], aZ1[4];
        #pragma unroll
        for (int b = 0; b < 4; b++) { aR0[b] = aR1[b] = aZ0[b] = aZ1[b] = 0ull; }
        #pragma unroll
        for (int i = 0; i < 8; i++) {
            int k = 32 * i + 2 * s;
            ull wr0 = *(const ull*)&sW[(0 * 32 + jl0) * 256 + k];
            ull wr1 = *(const ull*)&sW[(0 * 32 + jl1) * 256 + k];
            ull wz0 = *(const ull*)&sW[(1 * 32 + jl0) * 256 + k];
            ull wz1 = *(const ull*)&sW[(1 * 32 + jl1) * 256 + k];
            #pragma unroll
            for (int b = 0; b < 4; b++) {
                ull hb = *(const ull*)&sH[b * 256 + k];
                aR0[b] = f2fma(wr0, hb, aR0[b]);
                aR1[b] = f2fma(wr1, hb, aR1[b]);
                aZ0[b] = f2fma(wz0, hb, aZ0[b]);
                aZ1[b] = f2fma(wz1, hb, aZ1[b]);
            }
        }
        #pragma unroll
        for (int b = 0; b < 4; b++) {
            sPart[((0 + b) * 32 + jl0) * 16 + s] = f2sum(aR0[b]);
            sPart[((0 + b) * 32 + jl1) * 16 + s] = f2sum(aR1[b]);
            sPart[((4 + b) * 32 + jl0) * 16 + s] = f2sum(aZ0[b]);
            sPart[((4 + b) * 32 + jl1) * 16 + s] = f2sum(aZ1[b]);
        }
        __syncthreads();

        if (tid < 128) {
            float sr = 0.f, sz = 0.f;
            const float4* p4 = (const float4*)&sPart[(rb * 32 + rc) * 16];
            #pragma unroll
            for (int q = 0; q < 4; q++) { float4 v = p4[q]; sr += (v.x + v.y) + (v.z + v.w); }
            p4 = (const float4*)&sPart[((4 + rb) * 32 + rc) * 16];
            #pragma unroll
            for (int q = 0; q < 4; q++) { float4 v = p4[q]; sz += (v.x + v.y) + (v.z + v.w); }
            float r = __fdividef(1.0f, 1.0f + __expf(-(sr + gxr)));
            zloc    = __fdividef(1.0f, 1.0f + __expf(-(sz + gxz)));
            hloc = sH[rb * 256 + j0 + rc];
            float rh = r * hloc;
            #pragma unroll
            for (int p = 0; p < 8; p++)
                asm volatile("st.shared::cluster.f32 [%0], %1;" :: "r"(rh_peer[p]), "f"(rh) : "memory");
        }
        asm volatile("barrier.cluster.arrive.aligned;" ::: "memory");
        asm volatile("barrier.cluster.wait.aligned;"   ::: "memory");

        // ---- phase B: h-tilde matvec over sRH ----
        ull aH0[4], aH1[4];
        #pragma unroll
        for (int b = 0; b < 4; b++) { aH0[b] = aH1[b] = 0ull; }
        #pragma unroll
        for (int i = 0; i < 8; i++) {
            int k = 32 * i + 2 * s;
            ull wh0 = *(const ull*)&sW[(2 * 32 + jl0) * 256 + k];
            ull wh1 = *(const ull*)&sW[(2 * 32 + jl1) * 256 + k];
            #pragma unroll
            for (int b = 0; b < 4; b++) {
                ull rhb = *(const ull*)&sRH[b * 256 + k];
                aH0[b] = f2fma(wh0, rhb, aH0[b]);
                aH1[b] = f2fma(wh1, rhb, aH1[b]);
            }
        }
        #pragma unroll
        for (int b = 0; b < 4; b++) {
            sPart[(b * 32 + jl0) * 16 + s] = f2sum(aH0[b]);
            sPart[(b * 32 + jl1) * 16 + s] = f2sum(aH1[b]);
        }
        __syncthreads();

        if (tid < 128) {
            float sh = 0.f;
            const float4* p4 = (const float4*)&sPart[(rb * 32 + rc) * 16];
            #pragma unroll
            for (int q = 0; q < 4; q++) { float4 v = p4[q]; sh += (v.x + v.y) + (v.z + v.w); }
            // tanh(x) = 1 - 2/(exp(2x)+1)
            float e  = __expf(2.0f * (sh + gxh));
            float ht = 1.0f - __fdividef(2.0f, e + 1.0f);
            float hn = hloc + zloc * (ht - hloc);
            #pragma unroll
            for (int p = 0; p < 8; p++)
                asm volatile("st.shared::cluster.f32 [%0], %1;" :: "r"(h_peer[p]), "f"(hn) : "memory");
            g_hs[((size_t)t * NB + (b0 + rb)) * NH + j0 + rc] = hn;
            if (t == SQ - 1) hlast[(size_t)(b0 + rb) * NH + j0 + rc] = hn;
        }
        asm volatile("barrier.cluster.arrive.aligned;" ::: "memory");
        asm volatile("barrier.cluster.wait.aligned;"   ::: "memory");
    }
}

// =====================================================================
extern "C" void kernel_launch(void* const* d_in, const int* in_sizes, int n_in,
                              void* d_out, int out_size) {
    const float* x   = (const float*)d_in[0];
    const float* Wr  = (const float*)d_in[1];
    const float* br  = (const float*)d_in[2];
    const float* Wz  = (const float*)d_in[3];
    const float* bz  = (const float*)d_in[4];
    const float* Wh  = (const float*)d_in[5];
    const float* bh  = (const float*)d_in[6];
    const float* Wfc = (const float*)d_in[7];
    const float* bfc = (const float*)d_in[8];

    float* out   = (float*)d_out;                       // [B, S, O]
    float* hlast = out + (size_t)NB * SQ * NO;          // [B, H] (tuple 2nd elem)

    cudaFuncSetAttribute(gru_rec, cudaFuncAttributeMaxDynamicSharedMemorySize,
                         P2_SMEM_BYTES);

    // Phase 1: x-part preactivations for all 3 gates
    gemm_pre<<<dim3((NB * SQ) / 64, NH / 64, 3), 256>>>(x, Wr, Wz, Wh, br, bz, bh);

    // Phase 2: sequential recurrence (16 clusters x 8 CTAs)
    gru_rec<<<128, 256, P2_SMEM_BYTES>>>(Wr, Wz, Wh, hlast);

    // Phase 3: output projection
    gemm_fc<<<dim3((SQ * NB) / 64, NO / 64), 256>>>(Wfc, bfc, out);
}